// round 4
// baseline (speedup 1.0000x reference)
#include <cuda_runtime.h>
#include <math_constants.h>

#define EMB 128
#define FEAT (2 * EMB)
#define BATCH 8192
#define MAX_SEG 2048
#define NTHREADS 256
#define NWARPS (NTHREADS / 32)

__device__ int   g_seg_start[BATCH + 1];
__device__ float g_diag[EMB];            // diag(w) * fingerprint, precomputed

// ---------------------------------------------------------------------------
// Kernel 1: segment boundaries from sorted segment_ids + diag precompute.
// ---------------------------------------------------------------------------
__global__ void seg_bounds_kernel(const int* __restrict__ seg, int T,
                                  const float* __restrict__ w,
                                  const float* __restrict__ fp) {
    int i = blockIdx.x * blockDim.x + threadIdx.x;
    if (blockIdx.x == 0 && threadIdx.x < EMB) {
        g_diag[threadIdx.x] = w[threadIdx.x * (EMB + 1)] * fp[threadIdx.x];
    }
    if (i >= T) return;
    int sid  = seg[i];
    int prev = (i == 0) ? -1 : seg[i - 1];
    for (int b = prev + 1; b <= sid; ++b) g_seg_start[b] = i;
    if (i == T - 1) {
        for (int b = sid + 1; b <= BATCH; ++b) g_seg_start[b] = T;
    }
}

// ---------------------------------------------------------------------------
// Kernel 2: one block per segment.
// Phase 1: warp-per-token score + online weighted key-half accumulation,
//          with depth-1 software prefetch (key read exactly once).
// Phase 2: streams only `value` with the normalized weights.
// No initial __syncthreads: diag comes from a global, so streaming starts
// on cycle ~0 of the block.
// ---------------------------------------------------------------------------
__global__ __launch_bounds__(NTHREADS)
void fpattn_kernel(const float* __restrict__ value,
                   const float* __restrict__ key,
                   float* __restrict__ out)
{
    __shared__ float  s_wts[MAX_SEG];            // raw scores, then weights
    __shared__ float  s_red_m[NWARPS];
    __shared__ float  s_red_s[NWARPS];
    __shared__ float  s_stat[2];                 // [0]=smax, [1]=1/denom
    __shared__ float4 s_kacc[NWARPS][EMB / 4];   // per-warp scaled key partials
    __shared__ float4 s_acc[NTHREADS];           // value-half reduction

    const int b    = blockIdx.x;
    const int tid  = threadIdx.x;
    const int lane = tid & 31;
    const int warp = tid >> 5;

    const int s = g_seg_start[b];
    const int e = g_seg_start[b + 1];
    const int n = e - s;

    if (n == 0) {                                // must overwrite poisoned out
        out[(size_t)b * FEAT + tid] = 0.0f;
        return;
    }

    const float4 d4 = __ldg(((const float4*)g_diag) + lane);  // L1/L2-hot
    const float inv_scale = 0.08838834764831845f;             // 1/sqrt(128)

    if (n <= MAX_SEG) {
        // ---------- Phase 1: scores + online key accumulation ----------
        float  m = -CUDART_INF_F;                // per-warp running max (uniform)
        float  ssum = 0.f;
        float4 kacc = make_float4(0.f, 0.f, 0.f, 0.f);

        int i = s + warp;
        const float4* kptr = (const float4*)key + (size_t)i * (EMB / 4) + lane;
        float4 kc, kn;
        if (i < e) kc = __ldcs(kptr);
        while (i < e) {
            const int inext = i + NWARPS;
            if (inext < e) kn = __ldcs(kptr + NWARPS * (EMB / 4));  // prefetch
            float dot = kc.x * d4.x + kc.y * d4.y + kc.z * d4.z + kc.w * d4.w;
            #pragma unroll
            for (int o = 16; o; o >>= 1) dot += __shfl_xor_sync(0xffffffffu, dot, o);
            const float sc = dot * inv_scale;    // warp-uniform
            if (lane == 0) s_wts[i - s] = sc;
            if (sc <= m) {                       // uniform branch, common case
                float p = __expf(sc - m);
                ssum += p;
                kacc.x += p * kc.x; kacc.y += p * kc.y;
                kacc.z += p * kc.z; kacc.w += p * kc.w;
            } else {                             // new max: rescale history
                float r = __expf(m - sc);
                ssum = ssum * r + 1.0f;
                kacc.x = kacc.x * r + kc.x; kacc.y = kacc.y * r + kc.y;
                kacc.z = kacc.z * r + kc.z; kacc.w = kacc.w * r + kc.w;
                m = sc;
            }
            kc = kn;
            kptr += NWARPS * (EMB / 4);
            i = inext;
        }
        if (lane == 0) { s_red_m[warp] = m; s_red_s[warp] = ssum; }
        __syncthreads();
        if (tid == 0) {
            float smax = s_red_m[0];
            #pragma unroll
            for (int k = 1; k < NWARPS; ++k) smax = fmaxf(smax, s_red_m[k]);
            float denom = 0.f;
            #pragma unroll
            for (int k = 0; k < NWARPS; ++k)
                denom += s_red_s[k] * __expf(s_red_m[k] - smax);
            s_stat[0] = smax;
            s_stat[1] = 1.0f / denom;
        }
        __syncthreads();
        const float smax = s_stat[0];
        const float invd = s_stat[1];

        // publish scaled per-warp key partials; convert scores -> weights
        {
            const float scale_w = __expf(m - smax) * invd;   // 0 if warp empty
            s_kacc[warp][lane] = make_float4(kacc.x * scale_w, kacc.y * scale_w,
                                             kacc.z * scale_w, kacc.w * scale_w);
        }
        for (int j = tid; j < n; j += NTHREADS)
            s_wts[j] = __expf(s_wts[j] - smax) * invd;
        __syncthreads();

        // warp 1: reduce + store key half while others start phase 2
        if (warp == 1) {
            float4 t = s_kacc[0][lane];
            #pragma unroll
            for (int k = 1; k < NWARPS; ++k) {
                float4 u = s_kacc[k][lane];
                t.x += u.x; t.y += u.y; t.z += u.z; t.w += u.w;
            }
            ((float4*)(out + (size_t)b * FEAT + EMB))[lane] = t;
        }

        // ---------- Phase 2: value stream only, 8 tokens in flight ----------
        float4 acc = make_float4(0.f, 0.f, 0.f, 0.f);
        const float4* vptr = (const float4*)value + (size_t)(s + warp) * (EMB / 4) + lane;
        #pragma unroll 4
        for (int i2 = s + warp; i2 < e; i2 += NWARPS, vptr += NWARPS * (EMB / 4)) {
            float  wt = s_wts[i2 - s];
            float4 v  = __ldcs(vptr);
            acc.x += wt * v.x; acc.y += wt * v.y;
            acc.z += wt * v.z; acc.w += wt * v.w;
        }
        s_acc[tid] = acc;
        __syncthreads();
        if (tid < 32) {
            float4 a = s_acc[tid];
            #pragma unroll
            for (int k = 1; k < NWARPS; ++k) {
                float4 u = s_acc[tid + 32 * k];
                a.x += u.x; a.y += u.y; a.z += u.z; a.w += u.w;
            }
            ((float4*)(out + (size_t)b * FEAT))[tid] = a;
        }
        return;
    }

    // ================= Fallback: n > MAX_SEG (streaming, 3 passes) =========
    {
        // pass 1: max
        float lmax = -CUDART_INF_F;
        for (int i = s + warp; i < e; i += NWARPS) {
            float4 k4 = __ldg((const float4*)(key + (size_t)i * EMB) + lane);
            float dot = k4.x * d4.x + k4.y * d4.y + k4.z * d4.z + k4.w * d4.w;
            #pragma unroll
            for (int o = 16; o; o >>= 1) dot += __shfl_xor_sync(0xffffffffu, dot, o);
            lmax = fmaxf(lmax, dot * inv_scale);
        }
        if (lane == 0) s_red_m[warp] = lmax;
        __syncthreads();
        if (tid == 0) {
            float mm = s_red_m[0];
            #pragma unroll
            for (int k = 1; k < NWARPS; ++k) mm = fmaxf(mm, s_red_m[k]);
            s_stat[0] = mm;
        }
        __syncthreads();
        const float smax = s_stat[0];

        // pass 2: denom
        float lsum = 0.f;
        for (int i = s + warp; i < e; i += NWARPS) {
            float4 k4 = __ldg((const float4*)(key + (size_t)i * EMB) + lane);
            float dot = k4.x * d4.x + k4.y * d4.y + k4.z * d4.z + k4.w * d4.w;
            #pragma unroll
            for (int o = 16; o; o >>= 1) dot += __shfl_xor_sync(0xffffffffu, dot, o);
            if (lane == 0) lsum += __expf(dot * inv_scale - smax);
        }
        if (lane == 0) s_red_s[warp] = lsum;
        __syncthreads();
        if (tid == 0) {
            float t = 0.f;
            #pragma unroll
            for (int k = 0; k < NWARPS; ++k) t += s_red_s[k];
            s_stat[1] = 1.0f / t;
        }
        __syncthreads();
        const float invd = s_stat[1];

        // pass 3: chunked weights + concat accumulation
        const int tok_off = tid >> 6;            // 4 tokens in flight
        const int q       = tid & 63;            // 64 float4 cols of concat
        const float* fbase = (q < 32) ? value : key;
        const int col4     = (q < 32) ? q : (q - 32);
        float4 acc = make_float4(0.f, 0.f, 0.f, 0.f);

        for (int c0 = s; c0 < e; c0 += MAX_SEG) {
            const int c1 = min(c0 + MAX_SEG, e);
            for (int i = c0 + warp; i < c1; i += NWARPS) {
                float4 k4 = __ldg((const float4*)(key + (size_t)i * EMB) + lane);
                float dot = k4.x * d4.x + k4.y * d4.y + k4.z * d4.z + k4.w * d4.w;
                #pragma unroll
                for (int o = 16; o; o >>= 1) dot += __shfl_xor_sync(0xffffffffu, dot, o);
                if (lane == 0) s_wts[i - c0] = __expf(dot * inv_scale - smax) * invd;
            }
            __syncthreads();
            #pragma unroll 4
            for (int i = c0 + tok_off; i < c1; i += 4) {
                float  wt = s_wts[i - c0];
                float4 v  = __ldg((const float4*)(fbase + (size_t)i * EMB) + col4);
                acc.x += wt * v.x; acc.y += wt * v.y;
                acc.z += wt * v.z; acc.w += wt * v.w;
            }
            __syncthreads();
        }

        s_acc[tid] = acc;
        __syncthreads();
        if (tid < 64) {
            float4 a0 = s_acc[tid];
            float4 a1 = s_acc[tid + 64];
            float4 a2 = s_acc[tid + 128];
            float4 a3 = s_acc[tid + 192];
            a0.x += a1.x + a2.x + a3.x;
            a0.y += a1.y + a2.y + a3.y;
            a0.z += a1.z + a2.z + a3.z;
            a0.w += a1.w + a2.w + a3.w;
            ((float4*)(out + (size_t)b * FEAT))[tid] = a0;
        }
    }
}

// ---------------------------------------------------------------------------
extern "C" void kernel_launch(void* const* d_in, const int* in_sizes, int n_in,
                              void* d_out, int out_size) {
    const float* value = (const float*)d_in[0];
    const float* key   = (const float*)d_in[1];
    const int*   seg   = (const int*)d_in[2];
    const float* fp    = (const float*)d_in[3];
    const float* w     = (const float*)d_in[4];
    float* out = (float*)d_out;
    const int T = in_sizes[2];

    seg_bounds_kernel<<<(T + NTHREADS - 1) / NTHREADS, NTHREADS>>>(seg, T, w, fp);
    fpattn_kernel<<<BATCH, NTHREADS>>>(value, key, out);
}

// round 6
// speedup vs baseline: 1.0303x; 1.0303x over previous
#include <cuda_runtime.h>
#include <math_constants.h>

#define EMB 128
#define FEAT (2 * EMB)
#define BATCH 8192
#define MAX_SEG 2048
#define NTHREADS 256
#define NWARPS (NTHREADS / 32)

__device__ int   g_seg_start[BATCH + 1];
__device__ float g_diag[EMB];            // diag(w) * fingerprint, precomputed

// ---------------------------------------------------------------------------
// Kernel 1: segment boundaries from sorted segment_ids + diag precompute.
// ---------------------------------------------------------------------------
__global__ void seg_bounds_kernel(const int* __restrict__ seg, int T,
                                  const float* __restrict__ w,
                                  const float* __restrict__ fp) {
    int i = blockIdx.x * blockDim.x + threadIdx.x;
    if (blockIdx.x == 0 && threadIdx.x < EMB) {
        g_diag[threadIdx.x] = w[threadIdx.x * (EMB + 1)] * fp[threadIdx.x];
    }
    if (i >= T) return;
    int sid  = seg[i];
    int prev = (i == 0) ? -1 : seg[i - 1];
    for (int b = prev + 1; b <= sid; ++b) g_seg_start[b] = i;
    if (i == T - 1) {
        for (int b = sid + 1; b <= BATCH; ++b) g_seg_start[b] = T;
    }
}

// ---------------------------------------------------------------------------
// Kernel 2: one block per segment. Phase 1: warp-per-token score + online
// weighted key-half accumulation (key read exactly once, no prefetch —
// register budget <=32 keeps 64 warps/SM, which is what hides latency).
// Phase 2: streams only `value` with the normalized weights.
// ---------------------------------------------------------------------------
__global__ __launch_bounds__(NTHREADS, 8)
void fpattn_kernel(const float* __restrict__ value,
                   const float* __restrict__ key,
                   float* __restrict__ out)
{
    __shared__ float  s_wts[MAX_SEG];            // raw scores, then weights
    __shared__ float  s_red_m[NWARPS];
    __shared__ float  s_red_s[NWARPS];
    __shared__ float  s_stat[2];                 // [0]=smax, [1]=1/denom
    __shared__ float4 s_kacc[NWARPS][EMB / 4];   // per-warp scaled key partials
    __shared__ float4 s_acc[NTHREADS];           // value-half reduction

    const int b    = blockIdx.x;
    const int tid  = threadIdx.x;
    const int lane = tid & 31;
    const int warp = tid >> 5;

    const int s = g_seg_start[b];
    const int e = g_seg_start[b + 1];
    const int n = e - s;

    if (n == 0) {                                // must overwrite poisoned out
        out[(size_t)b * FEAT + tid] = 0.0f;
        return;
    }

    const float4 d4 = __ldg(((const float4*)g_diag) + lane);  // L1/L2-hot
    const float inv_scale = 0.08838834764831845f;             // 1/sqrt(128)

    if (n <= MAX_SEG) {
        // ---------- Phase 1: scores + online key accumulation ----------
        float  m = -CUDART_INF_F;                // per-warp running max (uniform)
        float  ssum = 0.f;
        float4 kacc = make_float4(0.f, 0.f, 0.f, 0.f);

        const float4* kptr = (const float4*)key + (size_t)(s + warp) * (EMB / 4) + lane;
        for (int i = s + warp; i < e; i += NWARPS, kptr += NWARPS * (EMB / 4)) {
            float4 k4 = __ldcs(kptr);
            float dot = k4.x * d4.x + k4.y * d4.y + k4.z * d4.z + k4.w * d4.w;
            #pragma unroll
            for (int o = 16; o; o >>= 1) dot += __shfl_xor_sync(0xffffffffu, dot, o);
            const float sc = dot * inv_scale;    // warp-uniform
            if (lane == 0) s_wts[i - s] = sc;
            if (sc <= m) {                       // uniform branch, common case
                float p = __expf(sc - m);
                ssum += p;
                kacc.x += p * k4.x; kacc.y += p * k4.y;
                kacc.z += p * k4.z; kacc.w += p * k4.w;
            } else {                             // new max: rescale history
                float r = __expf(m - sc);
                ssum = ssum * r + 1.0f;
                kacc.x = kacc.x * r + k4.x; kacc.y = kacc.y * r + k4.y;
                kacc.z = kacc.z * r + k4.z; kacc.w = kacc.w * r + k4.w;
                m = sc;
            }
        }
        if (lane == 0) { s_red_m[warp] = m; s_red_s[warp] = ssum; }
        __syncthreads();
        if (tid == 0) {
            float smax = s_red_m[0];
            #pragma unroll
            for (int k = 1; k < NWARPS; ++k) smax = fmaxf(smax, s_red_m[k]);
            float denom = 0.f;
            #pragma unroll
            for (int k = 0; k < NWARPS; ++k)
                denom += s_red_s[k] * __expf(s_red_m[k] - smax);
            s_stat[0] = smax;
            s_stat[1] = 1.0f / denom;
        }
        __syncthreads();
        const float smax = s_stat[0];
        const float invd = s_stat[1];

        // publish scaled per-warp key partials; convert scores -> weights
        {
            const float scale_w = __expf(m - smax) * invd;   // 0 if warp empty
            s_kacc[warp][lane] = make_float4(kacc.x * scale_w, kacc.y * scale_w,
                                             kacc.z * scale_w, kacc.w * scale_w);
        }
        for (int j = tid; j < n; j += NTHREADS)
            s_wts[j] = __expf(s_wts[j] - smax) * invd;
        __syncthreads();

        // warp 1: reduce + store key half while others start phase 2
        if (warp == 1) {
            float4 t = s_kacc[0][lane];
            #pragma unroll
            for (int k = 1; k < NWARPS; ++k) {
                float4 u = s_kacc[k][lane];
                t.x += u.x; t.y += u.y; t.z += u.z; t.w += u.w;
            }
            ((float4*)(out + (size_t)b * FEAT + EMB))[lane] = t;
        }

        // ---------- Phase 2: value stream only, 8 tokens in flight ----------
        float4 acc = make_float4(0.f, 0.f, 0.f, 0.f);
        const float4* vptr = (const float4*)value + (size_t)(s + warp) * (EMB / 4) + lane;
        #pragma unroll 4
        for (int i2 = s + warp; i2 < e; i2 += NWARPS, vptr += NWARPS * (EMB / 4)) {
            float  wt = s_wts[i2 - s];
            float4 v  = __ldcs(vptr);
            acc.x += wt * v.x; acc.y += wt * v.y;
            acc.z += wt * v.z; acc.w += wt * v.w;
        }
        s_acc[tid] = acc;
        __syncthreads();
        if (tid < 32) {
            float4 a = s_acc[tid];
            #pragma unroll
            for (int k = 1; k < NWARPS; ++k) {
                float4 u = s_acc[tid + 32 * k];
                a.x += u.x; a.y += u.y; a.z += u.z; a.w += u.w;
            }
            ((float4*)(out + (size_t)b * FEAT))[tid] = a;
        }
        return;
    }

    // ================= Fallback: n > MAX_SEG (streaming, 3 passes) =========
    {
        // pass 1: max
        float lmax = -CUDART_INF_F;
        for (int i = s + warp; i < e; i += NWARPS) {
            float4 k4 = __ldg((const float4*)(key + (size_t)i * EMB) + lane);
            float dot = k4.x * d4.x + k4.y * d4.y + k4.z * d4.z + k4.w * d4.w;
            #pragma unroll
            for (int o = 16; o; o >>= 1) dot += __shfl_xor_sync(0xffffffffu, dot, o);
            lmax = fmaxf(lmax, dot * inv_scale);
        }
        if (lane == 0) s_red_m[warp] = lmax;
        __syncthreads();
        if (tid == 0) {
            float mm = s_red_m[0];
            #pragma unroll
            for (int k = 1; k < NWARPS; ++k) mm = fmaxf(mm, s_red_m[k]);
            s_stat[0] = mm;
        }
        __syncthreads();
        const float smax = s_stat[0];

        // pass 2: denom
        float lsum = 0.f;
        for (int i = s + warp; i < e; i += NWARPS) {
            float4 k4 = __ldg((const float4*)(key + (size_t)i * EMB) + lane);
            float dot = k4.x * d4.x + k4.y * d4.y + k4.z * d4.z + k4.w * d4.w;
            #pragma unroll
            for (int o = 16; o; o >>= 1) dot += __shfl_xor_sync(0xffffffffu, dot, o);
            if (lane == 0) lsum += __expf(dot * inv_scale - smax);
        }
        if (lane == 0) s_red_s[warp] = lsum;
        __syncthreads();
        if (tid == 0) {
            float t = 0.f;
            #pragma unroll
            for (int k = 0; k < NWARPS; ++k) t += s_red_s[k];
            s_stat[1] = 1.0f / t;
        }
        __syncthreads();
        const float invd = s_stat[1];

        // pass 3: chunked weights + concat accumulation
        const int tok_off = tid >> 6;            // 4 tokens in flight
        const int q       = tid & 63;            // 64 float4 cols of concat
        const float* fbase = (q < 32) ? value : key;
        const int col4     = (q < 32) ? q : (q - 32);
        float4 acc = make_float4(0.f, 0.f, 0.f, 0.f);

        for (int c0 = s; c0 < e; c0 += MAX_SEG) {
            const int c1 = min(c0 + MAX_SEG, e);
            for (int i = c0 + warp; i < c1; i += NWARPS) {
                float4 k4 = __ldg((const float4*)(key + (size_t)i * EMB) + lane);
                float dot = k4.x * d4.x + k4.y * d4.y + k4.z * d4.z + k4.w * d4.w;
                #pragma unroll
                for (int o = 16; o; o >>= 1) dot += __shfl_xor_sync(0xffffffffu, dot, o);
                if (lane == 0) s_wts[i - c0] = __expf(dot * inv_scale - smax) * invd;
            }
            __syncthreads();
            #pragma unroll 4
            for (int i = c0 + tok_off; i < c1; i += 4) {
                float  wt = s_wts[i - c0];
                float4 v  = __ldg((const float4*)(fbase + (size_t)i * EMB) + col4);
                acc.x += wt * v.x; acc.y += wt * v.y;
                acc.z += wt * v.z; acc.w += wt * v.w;
            }
            __syncthreads();
        }

        s_acc[tid] = acc;
        __syncthreads();
        if (tid < 64) {
            float4 a0 = s_acc[tid];
            float4 a1 = s_acc[tid + 64];
            float4 a2 = s_acc[tid + 128];
            float4 a3 = s_acc[tid + 192];
            a0.x += a1.x + a2.x + a3.x;
            a0.y += a1.y + a2.y + a3.y;
            a0.z += a1.z + a2.z + a3.z;
            a0.w += a1.w + a2.w + a3.w;
            ((float4*)(out + (size_t)b * FEAT))[tid] = a0;
        }
    }
}

// ---------------------------------------------------------------------------
extern "C" void kernel_launch(void* const* d_in, const int* in_sizes, int n_in,
                              void* d_out, int out_size) {
    const float* value = (const float*)d_in[0];
    const float* key   = (const float*)d_in[1];
    const int*   seg   = (const int*)d_in[2];
    const float* fp    = (const float*)d_in[3];
    const float* w     = (const float*)d_in[4];
    float* out = (float*)d_out;
    const int T = in_sizes[2];

    seg_bounds_kernel<<<(T + NTHREADS - 1) / NTHREADS, NTHREADS>>>(seg, T, w, fp);
    fpattn_kernel<<<BATCH, NTHREADS>>>(value, key, out);
}